// round 10
// baseline (speedup 1.0000x reference)
#include <cuda_runtime.h>
#include <cstdint>

// Problem dims (fixed by reference)
#define BSZ  8
#define SDIM 2048
#define IDIM 1024
#define HDIM 4096
#define ODIM 1024
#define MDIM (BSZ * SDIM)   // 16384

// Scratch (no cudaMalloc allowed). All GEMM operands live in tile-packed,
// SW128-pre-swizzled layout (A: 128x32 16KB blocks, B: 256x32 32KB blocks).
__device__ float g_decay[(size_t)MDIM * IDIM];     // 64 MB (normal layout)
__device__ float g_combined[(size_t)MDIM * IDIM];  // 64 MB (A-packed, tf32)
__device__ float g_hidden[(size_t)MDIM * HDIM];    // 256 MB (A-packed, tf32)
__device__ float g_xr[(size_t)MDIM * IDIM];        // 64 MB (A-packed, tf32)
__device__ float g_wgr[(size_t)IDIM * IDIM];       // 4 MB  (B-packed, tf32)
__device__ float g_w1r[(size_t)HDIM * IDIM];       // 16 MB (B-packed, tf32)
__device__ float g_w2r[(size_t)ODIM * HDIM];       // 16 MB (B-packed, tf32)

// tcgen05 only exists in the arch-specific (sm_103a) compilation pass.
#if !defined(__CUDA_ARCH__) || defined(__CUDA_ARCH_FEAT_SM103_ALL) || \
    defined(__CUDA_ARCH_FEAT_SM100_ALL) || defined(__CUDA_ARCH_SPECIFIC__)
#define KUSE_TC 1
#else
#define KUSE_TC 0
#endif

// ---------------------------------------------------------------------------
// Common helpers
// ---------------------------------------------------------------------------
__device__ __forceinline__ uint32_t smem_u32(const void* p) {
    return (uint32_t)__cvta_generic_to_shared(p);
}
__device__ __forceinline__ float to_tf32(float x) {
    float r;
    asm("cvt.rna.tf32.f32 %0, %1;" : "=f"(r) : "f"(x));
    return r;
}
__device__ __forceinline__ uint32_t swz(uint32_t o) {  // SW128 swizzle
    return o ^ ((o >> 3) & 0x70);
}
// Packed byte offsets (element granularity)
__device__ __forceinline__ size_t apack_off(int m, int k, int K) {
    return ((size_t)(m >> 7) * (K >> 5) + (k >> 5)) * 16384 +
           swz((uint32_t)((m & 127) * 128 + (k & 31) * 4));
}
__device__ __forceinline__ size_t bpack_off(int n, int k, int K) {
    return ((size_t)(n >> 8) * (K >> 5) + (k >> 5)) * 32768 +
           swz((uint32_t)((n & 255) * 128 + (k & 31) * 4));
}

#if KUSE_TC
__device__ __forceinline__ void mbar_init(uint32_t a, uint32_t cnt) {
    asm volatile("mbarrier.init.shared.b64 [%0], %1;" ::"r"(a), "r"(cnt)
                 : "memory");
}
__device__ __forceinline__ void mbar_wait(uint32_t a, uint32_t parity) {
    asm volatile(
        "{\n\t.reg .pred P;\n"
        "W%=:\n\t"
        "mbarrier.try_wait.parity.acquire.cta.shared::cta.b64 P, [%0], %1, 0x989680;\n\t"
        "@P bra D%=;\n\t"
        "bra W%=;\n"
        "D%=:\n\t}"
        ::"r"(a), "r"(parity)
        : "memory");
}
__device__ __forceinline__ void mbar_expect_tx(uint32_t a, uint32_t bytes) {
    asm volatile("mbarrier.arrive.expect_tx.shared.b64 _, [%0], %1;" ::"r"(a),
                 "r"(bytes)
                 : "memory");
}
// Bulk async copy gmem->smem completing on an mbarrier (UBLKCP).
__device__ __forceinline__ void bulkcp(uint32_t d, const void* s, uint32_t n,
                                       uint32_t mb) {
    asm volatile(
        "cp.async.bulk.shared::cluster.global.mbarrier::complete_tx::bytes "
        "[%0], [%1], %2, [%3];"
        ::"r"(d), "l"(s), "r"(n), "r"(mb)
        : "memory");
}
__device__ __forceinline__ void mma_tf32(uint32_t d, uint64_t ad, uint64_t bd,
                                         uint32_t idesc, bool acc) {
    uint32_t en = acc ? 1u : 0u;
    asm volatile(
        "{\n\t.reg .pred p;\n\t"
        "setp.ne.u32 p, %4, 0;\n\t"
        "tcgen05.mma.cta_group::1.kind::tf32 [%0], %1, %2, %3, {%5,%5,%5,%5}, p;\n\t}"
        ::"r"(d), "l"(ad), "l"(bd), "r"(idesc), "r"(en), "r"(0u)
        : "memory");
}
#define LDTM_X32(r, a)                                                       \
    asm volatile(                                                            \
        "tcgen05.ld.sync.aligned.32x32b.x32.b32 "                            \
        "{%0,%1,%2,%3,%4,%5,%6,%7,%8,%9,%10,%11,%12,%13,%14,%15,"            \
        "%16,%17,%18,%19,%20,%21,%22,%23,%24,%25,%26,%27,%28,%29,%30,%31}, " \
        "[%32];"                                                             \
        : "=r"((r)[0]), "=r"((r)[1]), "=r"((r)[2]), "=r"((r)[3]),            \
          "=r"((r)[4]), "=r"((r)[5]), "=r"((r)[6]), "=r"((r)[7]),            \
          "=r"((r)[8]), "=r"((r)[9]), "=r"((r)[10]), "=r"((r)[11]),          \
          "=r"((r)[12]), "=r"((r)[13]), "=r"((r)[14]), "=r"((r)[15]),        \
          "=r"((r)[16]), "=r"((r)[17]), "=r"((r)[18]), "=r"((r)[19]),        \
          "=r"((r)[20]), "=r"((r)[21]), "=r"((r)[22]), "=r"((r)[23]),        \
          "=r"((r)[24]), "=r"((r)[25]), "=r"((r)[26]), "=r"((r)[27]),        \
          "=r"((r)[28]), "=r"((r)[29]), "=r"((r)[30]), "=r"((r)[31])         \
        : "r"(a))
#endif  // KUSE_TC

// ---------------------------------------------------------------------------
// GEMM: C[m,n] = act(sum_k A[m,k]*B[n,k] + bias[n]);  A,B tile-packed tf32.
// CTA tile 128x256, BK=32, 4-stage pipeline driven by ONE control thread:
//   DONE-wait (lag) -> 2x cp.async.bulk (expect_tx on FULL) -> FULL-wait
//   -> 4x tcgen05.mma -> commit DONE.  Extra commit to FINB after last tile
// releases the 8 epilogue warps (race-free: FINB is single-use).
// ---------------------------------------------------------------------------
#define BM 128
#define BN 256
#define TB_A 16384             // A stage: 128 rows x 128 B
#define TB_B 32768             // B stage: 256 rows x 128 B
#define TB_ST (TB_A + TB_B)    // 48 KB
#define STAGES 4
#define SMEM_REQ (STAGES * TB_ST + 1024 + 256)

static constexpr uint64_t DESC_BASE =
    (2ull << 61) | (1ull << 46) | (64ull << 32) | (1ull << 16);  // SW128 K-major
// idesc: dtype F32, a/btype TF32(2), N=256, M=128
#define IDESC ((1u << 4) | (2u << 7) | (2u << 10) | (32u << 17) | (8u << 24))

enum { EP_SIG = 0, EP_RELU = 1, EP_BIAS = 2 };

// PACKO: write C in A-packed layout (tf32-rounded) for the next GEMM.
template <int EP, bool PACKO>
__global__ void __launch_bounds__(256, 1)
gemm_tc(const float* __restrict__ A, const float* __restrict__ B,
        float* __restrict__ C, const float* __restrict__ bias, int M, int N,
        int K) {
    extern __shared__ char dsm[];
    const int tid  = threadIdx.x;
    const int warp = tid >> 5;
    const int lane = tid & 31;
    const int bm   = blockIdx.y * BM;
    const int bn   = blockIdx.x * BN;

#if KUSE_TC
    const uint32_t sb    = smem_u32(dsm);
    const uint32_t tiles = (sb + 1023u) & ~1023u;
    const uint32_t ctrl  = tiles + STAGES * TB_ST;
    const uint32_t FULLB = ctrl;               // 4 x 8B, cnt=1 (+tx)
    const uint32_t DONEB = ctrl + 32;          // 4 x 8B, cnt=1
    const uint32_t FINB  = ctrl + 64;          // 1 x 8B, cnt=1
    const uint32_t TPTR  = ctrl + 96;

    if (tid == 0) {
#pragma unroll
        for (int s = 0; s < STAGES; s++) {
            mbar_init(FULLB + 8 * s, 1);
            mbar_init(DONEB + 8 * s, 1);
        }
        mbar_init(FINB, 1);
    }
    if (warp == 0) {
        asm volatile(
            "tcgen05.alloc.cta_group::1.sync.aligned.shared::cta.b32 [%0], %1;"
            ::"r"(TPTR), "r"(256u)
            : "memory");
        asm volatile("tcgen05.relinquish_alloc_permit.cta_group::1.sync.aligned;");
    }
    __syncthreads();
    uint32_t tmem;
    asm volatile("ld.shared.b32 %0, [%1];" : "=r"(tmem) : "r"(TPTR));

    const int nk = K >> 5;

    if (tid == 0) {
        // ---------------- single control thread: loads + MMA --------------
        const char* Ap = (const char*)A;
        const char* Bp = (const char*)B;
        const size_t abase = (size_t)blockIdx.y * nk;  // A block row
        const size_t bbase = (size_t)blockIdx.x * nk;  // B block row

        auto issue = [&](int lt) {
            const int st = lt & (STAGES - 1);
            const uint32_t As = tiles + st * TB_ST;
            mbar_expect_tx(FULLB + 8 * st, TB_ST);
            bulkcp(As, Ap + (abase + lt) * (size_t)TB_A, TB_A, FULLB + 8 * st);
            bulkcp(As + TB_A, Bp + (bbase + lt) * (size_t)TB_B, TB_B,
                   FULLB + 8 * st);
        };

#pragma unroll
        for (int lt = 0; lt < STAGES - 1; lt++) issue(lt);

        for (int kt = 0; kt < nk; kt++) {
            const int lt = kt + STAGES - 1;
            if (lt < nk) {
                if (lt >= STAGES)  // stage last read by MMA of tile lt-STAGES
                    mbar_wait(DONEB + 8 * (lt & (STAGES - 1)),
                              (uint32_t)(((lt / STAGES) - 1) & 1));
                issue(lt);
            }
            const int st = kt & (STAGES - 1);
            mbar_wait(FULLB + 8 * st, (uint32_t)((kt / STAGES) & 1));
            const uint32_t As = tiles + st * TB_ST;
            const uint64_t ad = DESC_BASE | ((uint64_t)(As >> 4) & 0x3FFF);
            const uint64_t bd =
                DESC_BASE | ((uint64_t)((As + TB_A) >> 4) & 0x3FFF);
#pragma unroll
            for (int s = 0; s < 4; s++)  // 4 x K=8 steps (+32B each)
                mma_tf32(tmem, ad + 2 * s, bd + 2 * s, IDESC,
                         (kt > 0) || (s > 0));
            asm volatile(
                "tcgen05.commit.cta_group::1.mbarrier::arrive::one.shared::cluster.b64 [%0];"
                ::"r"(DONEB + 8 * st)
                : "memory");
        }
        // release epilogue: arrives after ALL issued MMAs complete
        asm volatile(
            "tcgen05.commit.cta_group::1.mbarrier::arrive::one.shared::cluster.b64 [%0];"
            ::"r"(FINB)
            : "memory");
    }

    // ---------------- epilogue: all 8 warps ----------------
    mbar_wait(FINB, 0);
    asm volatile("tcgen05.fence::after_thread_sync;" ::: "memory");

    const int wg  = warp >> 2;  // 0..1 -> 128-col half
    const int wq  = warp & 3;   // lane partition (rows)
    const uint32_t tpart = tmem + ((uint32_t)wq << 21);
    const int row = bm + wq * 32 + lane;
#pragma unroll
    for (int h = 0; h < 4; h++) {
        const int col0 = wg * 128 + h * 32;
        uint32_t r[32];
        LDTM_X32(r, tpart + col0);
        asm volatile("tcgen05.wait::ld.sync.aligned;" ::: "memory");
        float v[32];
#pragma unroll
        for (int j = 0; j < 32; j++) {
            float t = __uint_as_float(r[j]) + __ldg(&bias[bn + col0 + j]);
            if (EP == EP_RELU) t = fmaxf(t, 0.0f);
            if (EP == EP_SIG) t = 1.0f / (1.0f + __expf(-t));
            if (PACKO) t = to_tf32(t);
            v[j] = t;
        }
        if (PACKO) {
            // A-packed output block: row tile (row>>7), k-tile (bn+col0)>>5
            char* base = (char*)C +
                         ((size_t)(row >> 7) * (N >> 5) + ((bn + col0) >> 5)) *
                             16384;
            const uint32_t rr = (uint32_t)(row & 127) * 128;
#pragma unroll
            for (int q = 0; q < 8; q++)
                *(float4*)(base + swz(rr + q * 16)) =
                    make_float4(v[q * 4], v[q * 4 + 1], v[q * 4 + 2],
                                v[q * 4 + 3]);
        } else {
            float* dst = &C[(size_t)row * N + bn + col0];
#pragma unroll
            for (int q = 0; q < 8; q++)
                *(float4*)&dst[q * 4] = make_float4(v[q * 4], v[q * 4 + 1],
                                                    v[q * 4 + 2], v[q * 4 + 3]);
        }
    }

    __syncthreads();
    if (warp == 0)
        asm volatile("tcgen05.dealloc.cta_group::1.sync.aligned.b32 %0, %1;"
                     ::"r"(tmem), "r"(256u));

#else
    // ============ naive fallback (plain sm_103 pass; never runs) ==========
    for (int e = tid; e < BM * BN; e += 256) {
        const int r  = e / BN;
        const int cc = e % BN;
        const int m  = bm + r;
        const int n  = bn + cc;
        float acc = 0.0f;
        for (int k = 0; k < K; k++) {
            float a = *(const float*)((const char*)A + apack_off(m, k, K));
            float b = *(const float*)((const char*)B + bpack_off(n, k, K));
            acc += a * b;
        }
        float t = acc + bias[n];
        if (EP == EP_RELU) t = fmaxf(t, 0.0f);
        if (EP == EP_SIG) t = 1.0f / (1.0f + __expf(-t));
        if (PACKO) {
            *(float*)((char*)C + apack_off(m, n, N)) = to_tf32(t);
        } else {
            C[(size_t)m * N + n] = t;
        }
    }
#endif  // KUSE_TC
}

// ---------------------------------------------------------------------------
// Pack + round-to-tf32 prep (A layout: 128-row tiles; B layout: 256-row tiles)
// ---------------------------------------------------------------------------
template <int KSHIFT>
__global__ void pack_a_round(const float* __restrict__ in,
                             float* __restrict__ out, size_t n4) {
    const int K = 1 << KSHIFT;
    for (size_t i = (size_t)blockIdx.x * blockDim.x + threadIdx.x; i < n4;
         i += (size_t)gridDim.x * blockDim.x) {
        const size_t e = i * 4;
        const int m = (int)(e >> KSHIFT);
        const int k = (int)(e & (K - 1));
        float4 v = *(const float4*)(in + e);
        v.x = to_tf32(v.x); v.y = to_tf32(v.y);
        v.z = to_tf32(v.z); v.w = to_tf32(v.w);
        *(float4*)((char*)out + apack_off(m, k, K)) = v;
    }
}

template <int KSHIFT>
__global__ void pack_b_round(const float* __restrict__ in,
                             float* __restrict__ out, size_t n4) {
    const int K = 1 << KSHIFT;
    for (size_t i = (size_t)blockIdx.x * blockDim.x + threadIdx.x; i < n4;
         i += (size_t)gridDim.x * blockDim.x) {
        const size_t e = i * 4;
        const int n = (int)(e >> KSHIFT);
        const int k = (int)(e & (K - 1));
        float4 v = *(const float4*)(in + e);
        v.x = to_tf32(v.x); v.y = to_tf32(v.y);
        v.z = to_tf32(v.z); v.w = to_tf32(v.w);
        *(float4*)((char*)out + bpack_off(n, k, K)) = v;
    }
}

// ---------------------------------------------------------------------------
// Sequential buffer scan; writes combined in A-packed tf32 layout (K=IDIM).
// ---------------------------------------------------------------------------
__global__ void scan_kernel(const float* __restrict__ x,
                            const float* __restrict__ decay,
                            float* __restrict__ combined) {
    const int i = blockIdx.x * blockDim.x + threadIdx.x;  // channel (= k)
    const int b = blockIdx.y;
    const size_t base = (size_t)b * SDIM * IDIM + i;
    char* cb = (char*)combined;

    float buf = 0.0f;
    for (int t0 = 0; t0 < SDIM; t0 += 8) {
        float d[8], xv[8];
#pragma unroll
        for (int j = 0; j < 8; j++) {
            const size_t idx = base + (size_t)(t0 + j) * IDIM;
            d[j]  = decay[idx];
            xv[j] = x[idx];
        }
#pragma unroll
        for (int j = 0; j < 8; j++) {
            buf = buf * d[j] + (1.0f - d[j]) * xv[j];
            const int m = b * SDIM + t0 + j;  // GEMM row
            *(float*)(cb + apack_off(m, i, IDIM)) = to_tf32(xv[j] * d[j] + buf);
        }
    }
}

// ---------------------------------------------------------------------------
// Launch
// ---------------------------------------------------------------------------
extern "C" void kernel_launch(void* const* d_in, const int* in_sizes, int n_in,
                              void* d_out, int out_size) {
    (void)in_sizes; (void)n_in; (void)out_size;
    const float* x  = (const float*)d_in[0];
    const float* W1 = (const float*)d_in[1];
    const float* b1 = (const float*)d_in[2];
    const float* W2 = (const float*)d_in[3];
    const float* b2 = (const float*)d_in[4];
    const float* Wg = (const float*)d_in[5];
    const float* bg = (const float*)d_in[6];
    float* out = (float*)d_out;

    void *pd, *pc, *ph, *pxr, *pwg, *pw1, *pw2;
    cudaGetSymbolAddress(&pd, g_decay);
    cudaGetSymbolAddress(&pc, g_combined);
    cudaGetSymbolAddress(&ph, g_hidden);
    cudaGetSymbolAddress(&pxr, g_xr);
    cudaGetSymbolAddress(&pwg, g_wgr);
    cudaGetSymbolAddress(&pw1, g_w1r);
    cudaGetSymbolAddress(&pw2, g_w2r);
    float* decay    = (float*)pd;
    float* combined = (float*)pc;
    float* hidden   = (float*)ph;
    float* xr       = (float*)pxr;
    float* wgr      = (float*)pwg;
    float* w1r      = (float*)pw1;
    float* w2r      = (float*)pw2;

    cudaFuncSetAttribute(gemm_tc<EP_SIG, false>,
                         cudaFuncAttributeMaxDynamicSharedMemorySize, SMEM_REQ);
    cudaFuncSetAttribute(gemm_tc<EP_RELU, true>,
                         cudaFuncAttributeMaxDynamicSharedMemorySize, SMEM_REQ);
    cudaFuncSetAttribute(gemm_tc<EP_BIAS, false>,
                         cudaFuncAttributeMaxDynamicSharedMemorySize, SMEM_REQ);

    // pack + tf32-round prep
    pack_a_round<10><<<2048, 256>>>(x, xr, (size_t)MDIM * IDIM / 4);
    pack_b_round<10><<<256, 256>>>(Wg, wgr, (size_t)IDIM * IDIM / 4);
    pack_b_round<10><<<512, 256>>>(W1, w1r, (size_t)HDIM * IDIM / 4);
    pack_b_round<12><<<512, 256>>>(W2, w2r, (size_t)ODIM * HDIM / 4);

    // 1) decay = sigmoid(x @ Wg^T + bg)
    gemm_tc<EP_SIG, false><<<dim3(IDIM / BN, MDIM / BM), 256, SMEM_REQ>>>(
        xr, wgr, decay, bg, MDIM, IDIM, IDIM);
    // 2) recurrence -> combined (packed, tf32)
    scan_kernel<<<dim3(IDIM / 64, BSZ), 64>>>(x, decay, combined);
    // 3) hidden = relu(combined @ W1^T + b1) -> packed tf32
    gemm_tc<EP_RELU, true><<<dim3(HDIM / BN, MDIM / BM), 256, SMEM_REQ>>>(
        combined, w1r, hidden, b1, MDIM, HDIM, IDIM);
    // 4) out = hidden @ W2^T + b2  (normal layout)
    gemm_tc<EP_BIAS, false><<<dim3(ODIM / BN, MDIM / BM), 256, SMEM_REQ>>>(
        hidden, w2r, out, b2, MDIM, ODIM, HDIM);
}

// round 14
// speedup vs baseline: 1.2218x; 1.2218x over previous
#include <cuda_runtime.h>
#include <cstdint>

// Problem dims (fixed by reference)
#define BSZ  8
#define SDIM 2048
#define IDIM 1024
#define HDIM 4096
#define ODIM 1024
#define MDIM (BSZ * SDIM)   // 16384

// Scratch (no cudaMalloc allowed)
__device__ float g_decay[(size_t)MDIM * IDIM];     // 64 MB
__device__ float g_combined[(size_t)MDIM * IDIM];  // 64 MB (tf32-rounded)
__device__ float g_hidden[(size_t)MDIM * HDIM];    // 256 MB (tf32-rounded)
__device__ float g_xr[(size_t)MDIM * IDIM];        // 64 MB (tf32-rounded x)
__device__ float g_wgr[(size_t)IDIM * IDIM];       // 4 MB
__device__ float g_w1r[(size_t)HDIM * IDIM];       // 16 MB
__device__ float g_w2r[(size_t)ODIM * HDIM];       // 16 MB

// tcgen05 only exists in the arch-specific (sm_103a) compilation pass.
#if !defined(__CUDA_ARCH__) || defined(__CUDA_ARCH_FEAT_SM103_ALL) || \
    defined(__CUDA_ARCH_FEAT_SM100_ALL) || defined(__CUDA_ARCH_SPECIFIC__)
#define KUSE_TC 1
#else
#define KUSE_TC 0
#endif

// ---------------------------------------------------------------------------
// Common helpers
// ---------------------------------------------------------------------------
__device__ __forceinline__ uint32_t smem_u32(const void* p) {
    return (uint32_t)__cvta_generic_to_shared(p);
}
__device__ __forceinline__ float to_tf32(float x) {
    float r;
    asm("cvt.rna.tf32.f32 %0, %1;" : "=f"(r) : "f"(x));
    return r;
}
__device__ __forceinline__ void cp16(uint32_t s, const void* g) {
    asm volatile("cp.async.cg.shared.global [%0], [%1], 16;" ::"r"(s), "l"(g));
}

#if KUSE_TC
__device__ __forceinline__ void mbar_init(uint32_t a, uint32_t cnt) {
    asm volatile("mbarrier.init.shared.b64 [%0], %1;" ::"r"(a), "r"(cnt)
                 : "memory");
}
__device__ __forceinline__ void mbar_wait(uint32_t a, uint32_t parity) {
    asm volatile(
        "{\n\t.reg .pred P;\n"
        "W%=:\n\t"
        "mbarrier.try_wait.parity.acquire.cta.shared::cta.b64 P, [%0], %1, 0x989680;\n\t"
        "@P bra D%=;\n\t"
        "bra W%=;\n"
        "D%=:\n\t}"
        ::"r"(a), "r"(parity)
        : "memory");
}
__device__ __forceinline__ void mma_tf32(uint32_t d, uint64_t ad, uint64_t bd,
                                         uint32_t idesc, bool acc) {
    uint32_t en = acc ? 1u : 0u;
    asm volatile(
        "{\n\t.reg .pred p;\n\t"
        "setp.ne.u32 p, %4, 0;\n\t"
        "tcgen05.mma.cta_group::1.kind::tf32 [%0], %1, %2, %3, {%5,%5,%5,%5}, p;\n\t}"
        ::"r"(d), "l"(ad), "l"(bd), "r"(idesc), "r"(en), "r"(0u)
        : "memory");
}
#define LDTM_X32(r, a)                                                       \
    asm volatile(                                                            \
        "tcgen05.ld.sync.aligned.32x32b.x32.b32 "                            \
        "{%0,%1,%2,%3,%4,%5,%6,%7,%8,%9,%10,%11,%12,%13,%14,%15,"            \
        "%16,%17,%18,%19,%20,%21,%22,%23,%24,%25,%26,%27,%28,%29,%30,%31}, " \
        "[%32];"                                                             \
        : "=r"((r)[0]), "=r"((r)[1]), "=r"((r)[2]), "=r"((r)[3]),            \
          "=r"((r)[4]), "=r"((r)[5]), "=r"((r)[6]), "=r"((r)[7]),            \
          "=r"((r)[8]), "=r"((r)[9]), "=r"((r)[10]), "=r"((r)[11]),          \
          "=r"((r)[12]), "=r"((r)[13]), "=r"((r)[14]), "=r"((r)[15]),        \
          "=r"((r)[16]), "=r"((r)[17]), "=r"((r)[18]), "=r"((r)[19]),        \
          "=r"((r)[20]), "=r"((r)[21]), "=r"((r)[22]), "=r"((r)[23]),        \
          "=r"((r)[24]), "=r"((r)[25]), "=r"((r)[26]), "=r"((r)[27]),        \
          "=r"((r)[28]), "=r"((r)[29]), "=r"((r)[30]), "=r"((r)[31])         \
        : "r"(a))
#endif  // KUSE_TC

// ---------------------------------------------------------------------------
// GEMM: C[m,n] = act(sum_k A[m,k]*B[n,k] + bias[n])
// A [M,K] row-major, B [N,K] row-major, both tf32-rounded, normal layout.
// CTA tile 128x512, BK=32 (128B rows, SW128), 2-stage cp.async pipeline.
// Two N=256 MMA dispatches per K=8 step (D in TMEM cols 0 and 256).
// ---------------------------------------------------------------------------
#define BM 128
#define BN 512
#define TB_A 16384             // A stage: 128 rows x 128 B
#define TB_B 65536             // B stage: 512 rows x 128 B
#define TB_ST (TB_A + TB_B)    // 80 KB
#define STAGES 2
#define SMEM_REQ (STAGES * TB_ST + 1024 + 64)

static constexpr uint64_t DESC_BASE =
    (2ull << 61) | (1ull << 46) | (64ull << 32) | (1ull << 16);  // SW128 K-major
// idesc: dtype F32, a/btype TF32(2), N=256 (per dispatch), M=128
#define IDESC ((1u << 4) | (2u << 7) | (2u << 10) | (32u << 17) | (8u << 24))

enum { EP_SIG = 0, EP_RELU = 1, EP_BIAS = 2 };

template <int EP, bool ROUND>
__global__ void __launch_bounds__(256, 1)
gemm_tc(const float* __restrict__ A, const float* __restrict__ B,
        float* __restrict__ C, const float* __restrict__ bias, int M, int N,
        int K) {
    extern __shared__ char dsm[];
    const int tid  = threadIdx.x;
    const int warp = tid >> 5;
    const int lane = tid & 31;
    const int bm   = blockIdx.y * BM;
    const int bn   = blockIdx.x * BN;

#if KUSE_TC
    const uint32_t sb    = smem_u32(dsm);
    const uint32_t tiles = (sb + 1023u) & ~1023u;
    const uint32_t ctrl  = tiles + STAGES * TB_ST;
    const uint32_t DONEB = ctrl;              // 2 x 8B mbars
    const uint32_t TPTR  = ctrl + 32;

    if (tid == 0) {
#pragma unroll
        for (int s = 0; s < STAGES; s++) mbar_init(DONEB + 8 * s, 1);
    }
    if (warp == 0) {
        asm volatile(
            "tcgen05.alloc.cta_group::1.sync.aligned.shared::cta.b32 [%0], %1;"
            ::"r"(TPTR), "r"(512u)
            : "memory");
        asm volatile("tcgen05.relinquish_alloc_permit.cta_group::1.sync.aligned;");
    }
    __syncthreads();
    uint32_t tmem;
    asm volatile("ld.shared.b32 %0, [%1];" : "=r"(tmem) : "r"(TPTR));

    const int nk = K >> 5;  // 32-float k-tiles

    auto load_tile = [&](int st, int kt) {
        const uint32_t As = tiles + st * TB_ST;
        const uint32_t Bs = As + TB_A;
        const float* Ag = A + (size_t)bm * K + kt * 32;
        const float* Bg = B + (size_t)bn * K + kt * 32;
        // A: 1024 16B-chunks (4/thread)
#pragma unroll
        for (int t = 0; t < 4; t++) {
            const int ch = tid + t * 256;
            const int r  = ch >> 3;
            const int c  = ch & 7;
            uint32_t off = (uint32_t)(r * 128 + c * 16);
            off ^= (off >> 3) & 0x70;  // SW128 swizzle
            cp16(As + off, Ag + (size_t)r * K + c * 4);
        }
        // B: 4096 16B-chunks (16/thread)
#pragma unroll
        for (int t = 0; t < 16; t++) {
            const int ch = tid + t * 256;
            const int r  = ch >> 3;           // 0..511
            const int c  = ch & 7;
            uint32_t off = (uint32_t)(r * 128 + c * 16);
            off ^= (off >> 3) & 0x70;
            cp16(Bs + off, Bg + (size_t)r * K + c * 4);
        }
        asm volatile("cp.async.commit_group;");
    };

    load_tile(0, 0);

    for (int kt = 0; kt < nk; kt++) {
        const int tl = kt + 1;
        if (tl < nk) {
            if (tl >= STAGES)  // MMA that last read this buffer must be done
                mbar_wait(DONEB + 8 * (tl & 1),
                          (uint32_t)(((tl / STAGES) - 1) & 1));
            load_tile(tl & 1, tl);
            asm volatile("cp.async.wait_group 1;");  // tile kt resident
        } else {
            asm volatile("cp.async.wait_group 0;");  // last tile resident
        }
        __syncthreads();
        asm volatile("fence.proxy.async.shared::cta;" ::: "memory");
        if (tid == 0) {
            const uint32_t As = tiles + (kt & 1) * TB_ST;
            const uint64_t ad = DESC_BASE | ((uint64_t)(As >> 4) & 0x3FFF);
            const uint64_t bd0 =
                DESC_BASE | ((uint64_t)((As + TB_A) >> 4) & 0x3FFF);
            const uint64_t bd1 =
                DESC_BASE | ((uint64_t)((As + TB_A + 32768) >> 4) & 0x3FFF);
#pragma unroll
            for (int s = 0; s < 4; s++) {  // 4 x K=8 steps (+32B each)
                const bool acc = (kt > 0) || (s > 0);
                mma_tf32(tmem, ad + 2 * s, bd0 + 2 * s, IDESC, acc);
                mma_tf32(tmem + 256, ad + 2 * s, bd1 + 2 * s, IDESC, acc);
            }
            asm volatile(
                "tcgen05.commit.cta_group::1.mbarrier::arrive::one.shared::cluster.b64 [%0];"
                ::"r"(DONEB + 8 * (kt & 1))
                : "memory");
        }
        __syncthreads();  // all threads past wait_group before next overwrite
    }

    // drain: wait final tile's MMAs
    mbar_wait(DONEB + 8 * ((nk - 1) & 1), (uint32_t)(((nk - 1) / STAGES) & 1));
    asm volatile("tcgen05.fence::after_thread_sync;" ::: "memory");

    // ---------------- epilogue: TMEM -> bias/act -> gmem -------------------
    const int wg  = warp >> 2;  // 0..1 -> 256-col half
    const int wq  = warp & 3;   // lane partition (rows)
    const uint32_t tpart = tmem + ((uint32_t)wq << 21);
    const int row = bm + wq * 32 + lane;
#pragma unroll
    for (int h = 0; h < 8; h++) {
        const int col0 = wg * 256 + h * 32;
        uint32_t r[32];
        LDTM_X32(r, tpart + col0);
        asm volatile("tcgen05.wait::ld.sync.aligned;" ::: "memory");
        float v[32];
#pragma unroll
        for (int j = 0; j < 32; j++) {
            float t = __uint_as_float(r[j]) + __ldg(&bias[bn + col0 + j]);
            if (EP == EP_RELU) t = fmaxf(t, 0.0f);
            if (EP == EP_SIG) t = 1.0f / (1.0f + __expf(-t));
            if (ROUND) t = to_tf32(t);
            v[j] = t;
        }
        float* dst = &C[(size_t)row * N + bn + col0];
#pragma unroll
        for (int q = 0; q < 8; q++)
            *(float4*)&dst[q * 4] =
                make_float4(v[q * 4], v[q * 4 + 1], v[q * 4 + 2], v[q * 4 + 3]);
    }

    __syncthreads();
    if (warp == 0)
        asm volatile("tcgen05.dealloc.cta_group::1.sync.aligned.b32 %0, %1;"
                     ::"r"(tmem), "r"(512u));

#else
    // ============ naive fallback (plain sm_103 pass; never runs) ==========
    for (int e = tid; e < BM * BN; e += 256) {
        const int r  = e / BN;
        const int cc = e % BN;
        float acc = 0.0f;
        for (int k = 0; k < K; k++)
            acc += A[(size_t)(bm + r) * K + k] * B[(size_t)(bn + cc) * K + k];
        float t = acc + bias[bn + cc];
        if (EP == EP_RELU) t = fmaxf(t, 0.0f);
        if (EP == EP_SIG) t = 1.0f / (1.0f + __expf(-t));
        if (ROUND) t = to_tf32(t);
        C[(size_t)(bm + r) * N + bn + cc] = t;
    }
#endif  // KUSE_TC
}

// ---------------------------------------------------------------------------
// Round-to-nearest tf32 prep
// ---------------------------------------------------------------------------
__global__ void round_kernel(const float* __restrict__ in,
                             float* __restrict__ out, size_t n) {
    for (size_t i = (size_t)blockIdx.x * blockDim.x + threadIdx.x; i < n;
         i += (size_t)gridDim.x * blockDim.x)
        out[i] = to_tf32(in[i]);
}

// ---------------------------------------------------------------------------
// Sequential buffer scan; combined is tf32-rounded (GEMM A input).
// ---------------------------------------------------------------------------
__global__ void scan_kernel(const float* __restrict__ x,
                            const float* __restrict__ decay,
                            float* __restrict__ combined) {
    const int i = blockIdx.x * blockDim.x + threadIdx.x;
    const int b = blockIdx.y;
    const size_t base = (size_t)b * SDIM * IDIM + i;

    float buf = 0.0f;
    for (int t0 = 0; t0 < SDIM; t0 += 8) {
        float d[8], xv[8];
#pragma unroll
        for (int j = 0; j < 8; j++) {
            const size_t idx = base + (size_t)(t0 + j) * IDIM;
            d[j]  = decay[idx];
            xv[j] = x[idx];
        }
#pragma unroll
        for (int j = 0; j < 8; j++) {
            buf = buf * d[j] + (1.0f - d[j]) * xv[j];
            combined[base + (size_t)(t0 + j) * IDIM] = to_tf32(xv[j] * d[j] + buf);
        }
    }
}

// ---------------------------------------------------------------------------
// Launch
// ---------------------------------------------------------------------------
extern "C" void kernel_launch(void* const* d_in, const int* in_sizes, int n_in,
                              void* d_out, int out_size) {
    (void)in_sizes; (void)n_in; (void)out_size;
    const float* x  = (const float*)d_in[0];
    const float* W1 = (const float*)d_in[1];
    const float* b1 = (const float*)d_in[2];
    const float* W2 = (const float*)d_in[3];
    const float* b2 = (const float*)d_in[4];
    const float* Wg = (const float*)d_in[5];
    const float* bg = (const float*)d_in[6];
    float* out = (float*)d_out;

    void *pd, *pc, *ph, *pxr, *pwg, *pw1, *pw2;
    cudaGetSymbolAddress(&pd, g_decay);
    cudaGetSymbolAddress(&pc, g_combined);
    cudaGetSymbolAddress(&ph, g_hidden);
    cudaGetSymbolAddress(&pxr, g_xr);
    cudaGetSymbolAddress(&pwg, g_wgr);
    cudaGetSymbolAddress(&pw1, g_w1r);
    cudaGetSymbolAddress(&pw2, g_w2r);
    float* decay    = (float*)pd;
    float* combined = (float*)pc;
    float* hidden   = (float*)ph;
    float* xr       = (float*)pxr;
    float* wgr      = (float*)pwg;
    float* w1r      = (float*)pw1;
    float* w2r      = (float*)pw2;

    cudaFuncSetAttribute(gemm_tc<EP_SIG, false>,
                         cudaFuncAttributeMaxDynamicSharedMemorySize, SMEM_REQ);
    cudaFuncSetAttribute(gemm_tc<EP_RELU, true>,
                         cudaFuncAttributeMaxDynamicSharedMemorySize, SMEM_REQ);
    cudaFuncSetAttribute(gemm_tc<EP_BIAS, false>,
                         cudaFuncAttributeMaxDynamicSharedMemorySize, SMEM_REQ);

    // tf32 round-to-nearest prep (weights + x)
    round_kernel<<<1024, 256>>>(x, xr, (size_t)MDIM * IDIM);
    round_kernel<<<256, 256>>>(Wg, wgr, (size_t)IDIM * IDIM);
    round_kernel<<<512, 256>>>(W1, w1r, (size_t)HDIM * IDIM);
    round_kernel<<<512, 256>>>(W2, w2r, (size_t)ODIM * HDIM);

    // 1) decay = sigmoid(x @ Wg^T + bg)
    gemm_tc<EP_SIG, false><<<dim3(IDIM / BN, MDIM / BM), 256, SMEM_REQ>>>(
        xr, wgr, decay, bg, MDIM, IDIM, IDIM);
    // 2) recurrence -> combined (tf32-rounded)
    scan_kernel<<<dim3(IDIM / 64, BSZ), 64>>>(x, decay, combined);
    // 3) hidden = relu(combined @ W1^T + b1), tf32-rounded
    gemm_tc<EP_RELU, true><<<dim3(HDIM / BN, MDIM / BM), 256, SMEM_REQ>>>(
        combined, w1r, hidden, b1, MDIM, HDIM, IDIM);
    // 4) out = hidden @ W2^T + b2
    gemm_tc<EP_BIAS, false><<<dim3(ODIM / BN, MDIM / BM), 256, SMEM_REQ>>>(
        hidden, w2r, out, b2, MDIM, ODIM, HDIM);
}

// round 15
// speedup vs baseline: 1.4732x; 1.2057x over previous
#include <cuda_runtime.h>
#include <cstdint>

// Problem dims (fixed by reference)
#define BSZ  8
#define SDIM 2048
#define IDIM 1024
#define HDIM 4096
#define ODIM 1024
#define MDIM (BSZ * SDIM)   // 16384

// Scratch (no cudaMalloc allowed)
__device__ float g_decay[(size_t)MDIM * IDIM];     // 64 MB
__device__ float g_combined[(size_t)MDIM * IDIM];  // 64 MB (tf32-rounded)
__device__ float g_hidden[(size_t)MDIM * HDIM];    // 256 MB (tf32-rounded)
__device__ float g_xr[(size_t)MDIM * IDIM];        // 64 MB (tf32-rounded x)
__device__ float g_wgr[(size_t)IDIM * IDIM];       // 4 MB
__device__ float g_w1r[(size_t)HDIM * IDIM];       // 16 MB
__device__ float g_w2r[(size_t)ODIM * HDIM];       // 16 MB

// tcgen05 only exists in the arch-specific (sm_103a) compilation pass.
#if !defined(__CUDA_ARCH__) || defined(__CUDA_ARCH_FEAT_SM103_ALL) || \
    defined(__CUDA_ARCH_FEAT_SM100_ALL) || defined(__CUDA_ARCH_SPECIFIC__)
#define KUSE_TC 1
#else
#define KUSE_TC 0
#endif

// ---------------------------------------------------------------------------
// Common helpers
// ---------------------------------------------------------------------------
__device__ __forceinline__ uint32_t smem_u32(const void* p) {
    return (uint32_t)__cvta_generic_to_shared(p);
}
__device__ __forceinline__ float to_tf32(float x) {
    float r;
    asm("cvt.rna.tf32.f32 %0, %1;" : "=f"(r) : "f"(x));
    return r;
}
__device__ __forceinline__ void cp16(uint32_t s, const void* g) {
    asm volatile("cp.async.cg.shared.global [%0], [%1], 16;" ::"r"(s), "l"(g));
}

#if KUSE_TC
__device__ __forceinline__ void mbar_init(uint32_t a, uint32_t cnt) {
    asm volatile("mbarrier.init.shared.b64 [%0], %1;" ::"r"(a), "r"(cnt)
                 : "memory");
}
__device__ __forceinline__ void mbar_wait(uint32_t a, uint32_t parity) {
    asm volatile(
        "{\n\t.reg .pred P;\n"
        "W%=:\n\t"
        "mbarrier.try_wait.parity.acquire.cta.shared::cta.b64 P, [%0], %1, 0x989680;\n\t"
        "@P bra D%=;\n\t"
        "bra W%=;\n"
        "D%=:\n\t}"
        ::"r"(a), "r"(parity)
        : "memory");
}
__device__ __forceinline__ void mma_tf32(uint32_t d, uint64_t ad, uint64_t bd,
                                         uint32_t idesc, bool acc) {
    uint32_t en = acc ? 1u : 0u;
    asm volatile(
        "{\n\t.reg .pred p;\n\t"
        "setp.ne.u32 p, %4, 0;\n\t"
        "tcgen05.mma.cta_group::1.kind::tf32 [%0], %1, %2, %3, {%5,%5,%5,%5}, p;\n\t}"
        ::"r"(d), "l"(ad), "l"(bd), "r"(idesc), "r"(en), "r"(0u)
        : "memory");
}
#define LDTM_X32(r, a)                                                       \
    asm volatile(                                                            \
        "tcgen05.ld.sync.aligned.32x32b.x32.b32 "                            \
        "{%0,%1,%2,%3,%4,%5,%6,%7,%8,%9,%10,%11,%12,%13,%14,%15,"            \
        "%16,%17,%18,%19,%20,%21,%22,%23,%24,%25,%26,%27,%28,%29,%30,%31}, " \
        "[%32];"                                                             \
        : "=r"((r)[0]), "=r"((r)[1]), "=r"((r)[2]), "=r"((r)[3]),            \
          "=r"((r)[4]), "=r"((r)[5]), "=r"((r)[6]), "=r"((r)[7]),            \
          "=r"((r)[8]), "=r"((r)[9]), "=r"((r)[10]), "=r"((r)[11]),          \
          "=r"((r)[12]), "=r"((r)[13]), "=r"((r)[14]), "=r"((r)[15]),        \
          "=r"((r)[16]), "=r"((r)[17]), "=r"((r)[18]), "=r"((r)[19]),        \
          "=r"((r)[20]), "=r"((r)[21]), "=r"((r)[22]), "=r"((r)[23]),        \
          "=r"((r)[24]), "=r"((r)[25]), "=r"((r)[26]), "=r"((r)[27]),        \
          "=r"((r)[28]), "=r"((r)[29]), "=r"((r)[30]), "=r"((r)[31])         \
        : "r"(a))
#endif  // KUSE_TC

// ---------------------------------------------------------------------------
// GEMM: C[m,n] = act(sum_k A[m,k]*B[n,k] + bias[n])
// A [M,K] row-major, B [N,K] row-major, both tf32-rounded, normal layout.
// CTA tile 256(M) x 256(N): two 128-row A tiles + one 256-row B tile per
// BK=32 k-step; two M=128/N=256 MMA dispatches (D in TMEM cols 0 and 256).
// 3-stage cp.async pipeline (64 KB/stage).
// ---------------------------------------------------------------------------
#define BM 256
#define BN 256
#define TB_A 32768             // two A tiles: 2 x (128 rows x 128 B)
#define TB_B 32768             // B tile: 256 rows x 128 B
#define TB_ST (TB_A + TB_B)    // 64 KB
#define STAGES 3
#define SMEM_REQ (STAGES * TB_ST + 1024 + 64)

static constexpr uint64_t DESC_BASE =
    (2ull << 61) | (1ull << 46) | (64ull << 32) | (1ull << 16);  // SW128 K-major
// idesc: dtype F32, a/btype TF32(2), N=256 (per dispatch), M=128
#define IDESC ((1u << 4) | (2u << 7) | (2u << 10) | (32u << 17) | (8u << 24))

enum { EP_SIG = 0, EP_RELU = 1, EP_BIAS = 2 };

template <int EP, bool ROUND>
__global__ void __launch_bounds__(256, 1)
gemm_tc(const float* __restrict__ A, const float* __restrict__ B,
        float* __restrict__ C, const float* __restrict__ bias, int M, int N,
        int K) {
    extern __shared__ char dsm[];
    const int tid  = threadIdx.x;
    const int warp = tid >> 5;
    const int lane = tid & 31;
    const int bm   = blockIdx.y * BM;
    const int bn   = blockIdx.x * BN;

#if KUSE_TC
    const uint32_t sb    = smem_u32(dsm);
    const uint32_t tiles = (sb + 1023u) & ~1023u;
    const uint32_t ctrl  = tiles + STAGES * TB_ST;
    const uint32_t DONEB = ctrl;              // 3 x 8B mbars
    const uint32_t TPTR  = ctrl + 32;

    if (tid == 0) {
#pragma unroll
        for (int s = 0; s < STAGES; s++) mbar_init(DONEB + 8 * s, 1);
    }
    if (warp == 0) {
        asm volatile(
            "tcgen05.alloc.cta_group::1.sync.aligned.shared::cta.b32 [%0], %1;"
            ::"r"(TPTR), "r"(512u)
            : "memory");
        asm volatile("tcgen05.relinquish_alloc_permit.cta_group::1.sync.aligned;");
    }
    __syncthreads();
    uint32_t tmem;
    asm volatile("ld.shared.b32 %0, [%1];" : "=r"(tmem) : "r"(TPTR));

    const int nk = K >> 5;  // 32-float k-tiles

    auto load_tile = [&](int st, int kt) {
        const uint32_t As = tiles + st * TB_ST;   // A0 | A1 (16KB each)
        const uint32_t Bs = As + TB_A;
        const float* Ag = A + (size_t)bm * K + kt * 32;
        const float* Bg = B + (size_t)bn * K + kt * 32;
        // A: 2048 16B-chunks (8/thread), rows 0..255 split into two tiles
#pragma unroll
        for (int t = 0; t < 8; t++) {
            const int ch = tid + t * 256;          // 0..2047
            const int r  = ch >> 3;                // 0..255
            const int c  = ch & 7;                 // 16B chunk
            uint32_t off = (uint32_t)((r & 127) * 128 + c * 16);
            off ^= (off >> 3) & 0x70;              // SW128 swizzle
            cp16(As + (uint32_t)(r >> 7) * 16384u + off,
                 Ag + (size_t)r * K + c * 4);
        }
        // B: 2048 16B-chunks (8/thread), rows 0..255
#pragma unroll
        for (int t = 0; t < 8; t++) {
            const int ch = tid + t * 256;
            const int r  = ch >> 3;
            const int c  = ch & 7;
            uint32_t off = (uint32_t)(r * 128 + c * 16);
            off ^= (off >> 3) & 0x70;
            cp16(Bs + off, Bg + (size_t)r * K + c * 4);
        }
        asm volatile("cp.async.commit_group;");
    };

    load_tile(0, 0);
    load_tile(1, 1);

    for (int kt = 0; kt < nk; kt++) {
        asm volatile("cp.async.wait_group 1;");  // tile kt resident
        __syncthreads();
        asm volatile("fence.proxy.async.shared::cta;" ::: "memory");
        if (tid == 0) {
            const uint32_t As = tiles + (kt % STAGES) * TB_ST;
            const uint64_t ad0 = DESC_BASE | ((uint64_t)(As >> 4) & 0x3FFF);
            const uint64_t ad1 =
                DESC_BASE | ((uint64_t)((As + 16384) >> 4) & 0x3FFF);
            const uint64_t bd =
                DESC_BASE | ((uint64_t)((As + TB_A) >> 4) & 0x3FFF);
#pragma unroll
            for (int s = 0; s < 4; s++) {  // 4 x K=8 steps (+32B each)
                const bool acc = (kt > 0) || (s > 0);
                mma_tf32(tmem, ad0 + 2 * s, bd + 2 * s, IDESC, acc);
                mma_tf32(tmem + 256, ad1 + 2 * s, bd + 2 * s, IDESC, acc);
            }
            asm volatile(
                "tcgen05.commit.cta_group::1.mbarrier::arrive::one.shared::cluster.b64 [%0];"
                ::"r"(DONEB + 8 * (kt % STAGES))
                : "memory");
        }
        const int tl = kt + 2;
        if (tl < nk) {
            if (tl >= STAGES)  // MMA that last read this buffer must be done
                mbar_wait(DONEB + 8 * (tl % STAGES),
                          (uint32_t)(((tl / STAGES) - 1) & 1));
            load_tile(tl % STAGES, tl);
        } else {
            asm volatile("cp.async.commit_group;");  // keep group count moving
        }
        __syncthreads();
    }

    // drain: wait final tile's MMAs
    mbar_wait(DONEB + 8 * ((nk - 1) % STAGES),
              (uint32_t)(((nk - 1) / STAGES) & 1));
    asm volatile("tcgen05.fence::after_thread_sync;" ::: "memory");

    // ---------------- epilogue: TMEM -> bias/act -> gmem -------------------
    // warps 0-3: M-tile 0 (TMEM cols 0-255); warps 4-7: M-tile 1 (cols 256-511)
    const int mt  = warp >> 2;  // M-tile
    const int wq  = warp & 3;   // lane partition (rows)
    const uint32_t tpart = tmem + ((uint32_t)wq << 21);
    const int row = bm + mt * 128 + wq * 32 + lane;
#pragma unroll
    for (int h = 0; h < 8; h++) {
        const int tcol = mt * 256 + h * 32;   // TMEM column
        const int ncol = h * 32;              // output column within tile
        uint32_t r[32];
        LDTM_X32(r, tpart + tcol);
        asm volatile("tcgen05.wait::ld.sync.aligned;" ::: "memory");
        float v[32];
#pragma unroll
        for (int j = 0; j < 32; j++) {
            float t = __uint_as_float(r[j]) + __ldg(&bias[bn + ncol + j]);
            if (EP == EP_RELU) t = fmaxf(t, 0.0f);
            if (EP == EP_SIG) t = 1.0f / (1.0f + __expf(-t));
            if (ROUND) t = to_tf32(t);
            v[j] = t;
        }
        float* dst = &C[(size_t)row * N + bn + ncol];
#pragma unroll
        for (int q = 0; q < 8; q++)
            *(float4*)&dst[q * 4] =
                make_float4(v[q * 4], v[q * 4 + 1], v[q * 4 + 2], v[q * 4 + 3]);
    }

    __syncthreads();
    if (warp == 0)
        asm volatile("tcgen05.dealloc.cta_group::1.sync.aligned.b32 %0, %1;"
                     ::"r"(tmem), "r"(512u));

#else
    // ============ naive fallback (plain sm_103 pass; never runs) ==========
    for (int e = tid; e < BM * BN; e += 256) {
        const int r  = e / BN;
        const int cc = e % BN;
        float acc = 0.0f;
        for (int k = 0; k < K; k++)
            acc += A[(size_t)(bm + r) * K + k] * B[(size_t)(bn + cc) * K + k];
        float t = acc + bias[bn + cc];
        if (EP == EP_RELU) t = fmaxf(t, 0.0f);
        if (EP == EP_SIG) t = 1.0f / (1.0f + __expf(-t));
        if (ROUND) t = to_tf32(t);
        C[(size_t)(bm + r) * N + bn + cc] = t;
    }
#endif  // KUSE_TC
}

// ---------------------------------------------------------------------------
// Round-to-nearest tf32 prep
// ---------------------------------------------------------------------------
__global__ void round_kernel(const float* __restrict__ in,
                             float* __restrict__ out, size_t n) {
    for (size_t i = (size_t)blockIdx.x * blockDim.x + threadIdx.x; i < n;
         i += (size_t)gridDim.x * blockDim.x)
        out[i] = to_tf32(in[i]);
}

// ---------------------------------------------------------------------------
// Sequential buffer scan; combined is tf32-rounded (GEMM A input).
// ---------------------------------------------------------------------------
__global__ void scan_kernel(const float* __restrict__ x,
                            const float* __restrict__ decay,
                            float* __restrict__ combined) {
    const int i = blockIdx.x * blockDim.x + threadIdx.x;
    const int b = blockIdx.y;
    const size_t base = (size_t)b * SDIM * IDIM + i;

    float buf = 0.0f;
    for (int t0 = 0; t0 < SDIM; t0 += 8) {
        float d[8], xv[8];
#pragma unroll
        for (int j = 0; j < 8; j++) {
            const size_t idx = base + (size_t)(t0 + j) * IDIM;
            d[j]  = decay[idx];
            xv[j] = x[idx];
        }
#pragma unroll
        for (int j = 0; j < 8; j++) {
            buf = buf * d[j] + (1.0f - d[j]) * xv[j];
            combined[base + (size_t)(t0 + j) * IDIM] = to_tf32(xv[j] * d[j] + buf);
        }
    }
}

// ---------------------------------------------------------------------------
// Launch
// ---------------------------------------------------------------------------
extern "C" void kernel_launch(void* const* d_in, const int* in_sizes, int n_in,
                              void* d_out, int out_size) {
    (void)in_sizes; (void)n_in; (void)out_size;
    const float* x  = (const float*)d_in[0];
    const float* W1 = (const float*)d_in[1];
    const float* b1 = (const float*)d_in[2];
    const float* W2 = (const float*)d_in[3];
    const float* b2 = (const float*)d_in[4];
    const float* Wg = (const float*)d_in[5];
    const float* bg = (const float*)d_in[6];
    float* out = (float*)d_out;

    void *pd, *pc, *ph, *pxr, *pwg, *pw1, *pw2;
    cudaGetSymbolAddress(&pd, g_decay);
    cudaGetSymbolAddress(&pc, g_combined);
    cudaGetSymbolAddress(&ph, g_hidden);
    cudaGetSymbolAddress(&pxr, g_xr);
    cudaGetSymbolAddress(&pwg, g_wgr);
    cudaGetSymbolAddress(&pw1, g_w1r);
    cudaGetSymbolAddress(&pw2, g_w2r);
    float* decay    = (float*)pd;
    float* combined = (float*)pc;
    float* hidden   = (float*)ph;
    float* xr       = (float*)pxr;
    float* wgr      = (float*)pwg;
    float* w1r      = (float*)pw1;
    float* w2r      = (float*)pw2;

    cudaFuncSetAttribute(gemm_tc<EP_SIG, false>,
                         cudaFuncAttributeMaxDynamicSharedMemorySize, SMEM_REQ);
    cudaFuncSetAttribute(gemm_tc<EP_RELU, true>,
                         cudaFuncAttributeMaxDynamicSharedMemorySize, SMEM_REQ);
    cudaFuncSetAttribute(gemm_tc<EP_BIAS, false>,
                         cudaFuncAttributeMaxDynamicSharedMemorySize, SMEM_REQ);

    // tf32 round-to-nearest prep (weights + x)
    round_kernel<<<1024, 256>>>(x, xr, (size_t)MDIM * IDIM);
    round_kernel<<<256, 256>>>(Wg, wgr, (size_t)IDIM * IDIM);
    round_kernel<<<512, 256>>>(W1, w1r, (size_t)HDIM * IDIM);
    round_kernel<<<512, 256>>>(W2, w2r, (size_t)ODIM * HDIM);

    // 1) decay = sigmoid(x @ Wg^T + bg)
    gemm_tc<EP_SIG, false><<<dim3(IDIM / BN, MDIM / BM), 256, SMEM_REQ>>>(
        xr, wgr, decay, bg, MDIM, IDIM, IDIM);
    // 2) recurrence -> combined (tf32-rounded)
    scan_kernel<<<dim3(IDIM / 64, BSZ), 64>>>(x, decay, combined);
    // 3) hidden = relu(combined @ W1^T + b1), tf32-rounded
    gemm_tc<EP_RELU, true><<<dim3(HDIM / BN, MDIM / BM), 256, SMEM_REQ>>>(
        combined, w1r, hidden, b1, MDIM, HDIM, IDIM);
    // 4) out = hidden @ W2^T + b2
    gemm_tc<EP_BIAS, false><<<dim3(ODIM / BN, MDIM / BM), 256, SMEM_REQ>>>(
        hidden, w2r, out, b2, MDIM, ODIM, HDIM);
}